// round 8
// baseline (speedup 1.0000x reference)
#include <cuda_runtime.h>

#define LAMBDA_COORD 5.0f
#define LAMBDA_NO_OBJ 0.5f

#define NTHREADS 1024
#define NBLOCKS  148

// Specialized shape (the bench problem). Host verifies and falls back if different.
#define SNP4   327680     // prob float4-pairs total
#define SP     32768      // box items total
#define SCHUNK 2216       // float4-pairs per block: 2216*16B = 128B*277, aligned
#define SBCH   224        // box items per block (warp multiple)

__global__ void zero_out_kernel(float* out) { out[0] = 0.0f; }

__device__ __forceinline__ float warp_reduce(float v) {
    #pragma unroll
    for (int off = 16; off > 0; off >>= 1)
        v += __shfl_xor_sync(0xFFFFFFFFu, v, off);
    return v;
}

__device__ __forceinline__ void block_reduce_atomic(float acc, float* out) {
    __shared__ float warp_sums[NTHREADS >> 5];
    float wsum = warp_reduce(acc);
    int lane = threadIdx.x & 31;
    int wid  = threadIdx.x >> 5;
    if (lane == 0) warp_sums[wid] = wsum;
    __syncthreads();
    if (wid == 0) {
        float v = (lane < (NTHREADS >> 5)) ? warp_sums[lane] : 0.0f;
        v = warp_reduce(v);
        if (lane == 0) atomicAdd(out, v);
    }
}

__device__ __forceinline__ float box_term(
    const float* __restrict__ main_boxes, int mm, float4 pb, float cf, float miou)
{
    if (mm >= 0) {
        const float* mbp = main_boxes + (size_t)mm * 4;   // 16KB table, cache hits
        float dx = mbp[0] - pb.x;
        float dy = mbp[1] - pb.y;
        float sw = sqrtf(fmaxf(mbp[2], 0.0f)) - sqrtf(fmaxf(pb.z, 0.0f));
        float sh = sqrtf(fmaxf(mbp[3], 0.0f)) - sqrtf(fmaxf(pb.w, 0.0f));
        float di = miou - cf;
        return LAMBDA_COORD * (dx * dx + dy * dy + sw * sw + sh * sh) + di * di;
    }
    return LAMBDA_NO_OBJ * cf * cf;
}

// ===================== specialized kernel (bench shape) =====================
__global__ void __launch_bounds__(NTHREADS)
yolo_loss_spec(
    const float*  __restrict__ main_boxes,
    const float4* __restrict__ pred_boxes,
    const float*  __restrict__ conf,
    const float4* __restrict__ gmp,
    const float4* __restrict__ gpp,
    const int*    __restrict__ matched_main,
    const float*  __restrict__ matched_iou,
    float* __restrict__ out)
{
    const int b  = blockIdx.x;
    const int tx = threadIdx.x;

    const int pbase = b * SCHUNK;
    const int pend  = min(pbase + SCHUNK, SNP4);   // last block: 2088 fewer
    const int i0 = pbase + tx;
    const int i1 = i0 + NTHREADS;
    const int i2 = i1 + NTHREADS;
    const bool v1 = i1 < pend;                      // false only in last block tail
    const bool v2 = i2 < pend;                      // threads 0..167 (or last block)

    // box slice: block-uniform predicate (b*SBCH < SP  <=>  b < 147)
    const int  p       = b * SBCH + tx;
    const bool has_box = (tx < SBCH) && (p < SP);

    // ===== ONE independent front batch =====
    float4 a0 = gmp[i0];
    float4 c0 = gpp[i0];
    float4 a1, c1, a2, c2;
    if (v1) { a1 = gmp[i1]; c1 = gpp[i1]; }
    if (v2) { a2 = gmp[i2]; c2 = gpp[i2]; }

    int   mm = 0; float cf = 0.0f, miou = 0.0f;
    float4 pb = make_float4(0.f, 0.f, 0.f, 0.f);
    if (has_box) {
        mm   = matched_main[p];
        cf   = conf[p];
        miou = matched_iou[p];
        pb   = pred_boxes[p];
    }

    // ===== compute =====
    float acc = 0.0f, d;
    d = a0.x - c0.x; acc = fmaf(d, d, acc);
    d = a0.y - c0.y; acc = fmaf(d, d, acc);
    d = a0.z - c0.z; acc = fmaf(d, d, acc);
    d = a0.w - c0.w; acc = fmaf(d, d, acc);
    if (v1) {
        d = a1.x - c1.x; acc = fmaf(d, d, acc);
        d = a1.y - c1.y; acc = fmaf(d, d, acc);
        d = a1.z - c1.z; acc = fmaf(d, d, acc);
        d = a1.w - c1.w; acc = fmaf(d, d, acc);
    }
    if (v2) {
        d = a2.x - c2.x; acc = fmaf(d, d, acc);
        d = a2.y - c2.y; acc = fmaf(d, d, acc);
        d = a2.z - c2.z; acc = fmaf(d, d, acc);
        d = a2.w - c2.w; acc = fmaf(d, d, acc);
    }
    if (has_box)
        acc += box_term(main_boxes, mm, pb, cf, miou);

    block_reduce_atomic(acc, out);
}

// ===================== generic fallback (any shape) =====================
__global__ void __launch_bounds__(NTHREADS)
yolo_loss_generic(
    const float*  __restrict__ main_boxes,
    const float4* __restrict__ pred_boxes,
    const float*  __restrict__ conf,
    const float4* __restrict__ gmp,
    const float4* __restrict__ gpp,
    const int*    __restrict__ matched_main,
    const float*  __restrict__ matched_iou,
    float* __restrict__ out,
    int P, int NP4)
{
    const int tid    = blockIdx.x * NTHREADS + threadIdx.x;
    const int stride = gridDim.x * NTHREADS;
    float acc = 0.0f;

    for (int i = tid; i < NP4; i += stride) {
        float4 a = gmp[i];
        float4 c = gpp[i];
        float d;
        d = a.x - c.x; acc = fmaf(d, d, acc);
        d = a.y - c.y; acc = fmaf(d, d, acc);
        d = a.z - c.z; acc = fmaf(d, d, acc);
        d = a.w - c.w; acc = fmaf(d, d, acc);
    }
    for (int q = tid; q < P; q += stride) {
        int mm = matched_main[q];
        acc += box_term(main_boxes, mm, pred_boxes[q], conf[q], matched_iou[q]);
    }
    block_reduce_atomic(acc, out);
}

extern "C" void kernel_launch(void* const* d_in, const int* in_sizes, int n_in,
                              void* d_out, int out_size) {
    const float*  main_boxes   = (const float*) d_in[0];
    const float4* pred_boxes   = (const float4*)d_in[1];
    const float*  conf         = (const float*) d_in[2];
    const float4* gmp          = (const float4*)d_in[3];
    const float4* gpp          = (const float4*)d_in[4];
    const int*    matched_main = (const int*)   d_in[5];
    const float*  matched_iou  = (const float*) d_in[6];
    float* out = (float*)d_out;

    int P   = in_sizes[2];
    int NP4 = in_sizes[3] / 4;

    zero_out_kernel<<<1, 1>>>(out);

    if (P == SP && NP4 == SNP4) {
        yolo_loss_spec<<<NBLOCKS, NTHREADS>>>(
            main_boxes, pred_boxes, conf, gmp, gpp, matched_main, matched_iou, out);
    } else {
        yolo_loss_generic<<<NBLOCKS, NTHREADS>>>(
            main_boxes, pred_boxes, conf, gmp, gpp, matched_main, matched_iou,
            out, P, NP4);
    }
}

// round 9
// speedup vs baseline: 1.1507x; 1.1507x over previous
#include <cuda_runtime.h>

#define LAMBDA_COORD 5.0f
#define LAMBDA_NO_OBJ 0.5f

#define NTHREADS 1024
#define NBLOCKS  148    // one CTA per SM, single wave

__global__ void zero_out_kernel(float* out) {
    out[0] = 0.0f;
}

__device__ __forceinline__ float warp_reduce(float v) {
    #pragma unroll
    for (int off = 16; off > 0; off >>= 1)
        v += __shfl_xor_sync(0xFFFFFFFFu, v, off);
    return v;
}

// ===== R7 kernel verbatim (proven 7.2us, regs=48, fully-batched LDGs) =====
// plus one PDL sync immediately before the atomic tail.
__global__ void __launch_bounds__(NTHREADS)
yolo_loss_kernel(
    const float*  __restrict__ main_boxes,   // [M,4]
    const float4* __restrict__ pred_boxes,   // [P]
    const float*  __restrict__ conf,         // [P]
    const float4* __restrict__ gmp,          // [NP4]
    const float4* __restrict__ gpp,          // [NP4]
    const int*    __restrict__ matched_main, // [P]
    const float*  __restrict__ matched_iou,  // [P]
    float* __restrict__ out,
    int P, int NP4, int chunk, int bchunk)
{
    const int b  = blockIdx.x;
    const int tx = threadIdx.x;

    const int pbase = b * chunk;
    const int pend  = min(pbase + chunk, NP4);
    const int bbase = b * bchunk;

    float acc = 0.0f;

    const int i0 = pbase + tx;
    const int i1 = i0 + NTHREADS;
    const int i2 = i1 + NTHREADS;
    const bool v0 = i0 < pend;
    const bool v1 = i1 < pend;
    const bool v2 = i2 < pend;

    float4 a0, c0, a1, c1, a2, c2;
    if (v0) { a0 = gmp[i0]; c0 = gpp[i0]; }
    if (v1) { a1 = gmp[i1]; c1 = gpp[i1]; }
    if (v2) { a2 = gmp[i2]; c2 = gpp[i2]; }

    const int  p       = bbase + tx;
    const bool has_box = (tx < bchunk) && (p < P);
    int   mm = 0;
    float cf = 0.0f, miou = 0.0f;
    float4 pb = make_float4(0.f, 0.f, 0.f, 0.f);
    if (has_box) {
        mm   = matched_main[p];
        cf   = conf[p];
        miou = matched_iou[p];
        pb   = pred_boxes[p];
    }

    float d;
    if (v0) {
        d = a0.x - c0.x; acc = fmaf(d, d, acc);
        d = a0.y - c0.y; acc = fmaf(d, d, acc);
        d = a0.z - c0.z; acc = fmaf(d, d, acc);
        d = a0.w - c0.w; acc = fmaf(d, d, acc);
    }
    if (v1) {
        d = a1.x - c1.x; acc = fmaf(d, d, acc);
        d = a1.y - c1.y; acc = fmaf(d, d, acc);
        d = a1.z - c1.z; acc = fmaf(d, d, acc);
        d = a1.w - c1.w; acc = fmaf(d, d, acc);
    }
    if (v2) {
        d = a2.x - c2.x; acc = fmaf(d, d, acc);
        d = a2.y - c2.y; acc = fmaf(d, d, acc);
        d = a2.z - c2.z; acc = fmaf(d, d, acc);
        d = a2.w - c2.w; acc = fmaf(d, d, acc);
    }

    // generic spill loop (empty at this problem size; keeps codegen honest)
    for (int i = pbase + tx + 3 * NTHREADS; i < pend; i += NTHREADS) {
        float4 a = gmp[i];
        float4 c = gpp[i];
        d = a.x - c.x; acc = fmaf(d, d, acc);
        d = a.y - c.y; acc = fmaf(d, d, acc);
        d = a.z - c.z; acc = fmaf(d, d, acc);
        d = a.w - c.w; acc = fmaf(d, d, acc);
    }

    if (has_box) {
        if (mm >= 0) {
            const float* mbp = main_boxes + (size_t)mm * 4;
            float mx = mbp[0], my = mbp[1], mw = mbp[2], mh = mbp[3];

            float dx = mx - pb.x;
            float dy = my - pb.y;
            float xy = dx * dx + dy * dy;

            float sw = sqrtf(fmaxf(mw, 0.0f)) - sqrtf(fmaxf(pb.z, 0.0f));
            float sh = sqrtf(fmaxf(mh, 0.0f)) - sqrtf(fmaxf(pb.w, 0.0f));
            float wh = sw * sw + sh * sh;

            float di = miou - cf;
            acc += LAMBDA_COORD * (xy + wh) + di * di;
        } else {
            acc += LAMBDA_NO_OBJ * cf * cf;
        }
    }

    for (int q = bbase + tx + NTHREADS; q < min(bbase + bchunk, P); q += NTHREADS) {
        int   m2  = matched_main[q];
        float c2f = conf[q];
        if (m2 >= 0) {
            float4 pq = pred_boxes[q];
            const float* mbp = main_boxes + (size_t)m2 * 4;
            float dx = mbp[0] - pq.x;
            float dy = mbp[1] - pq.y;
            float sw = sqrtf(fmaxf(mbp[2], 0.0f)) - sqrtf(fmaxf(pq.z, 0.0f));
            float sh = sqrtf(fmaxf(mbp[3], 0.0f)) - sqrtf(fmaxf(pq.w, 0.0f));
            float di = matched_iou[q] - c2f;
            acc += LAMBDA_COORD * (dx * dx + dy * dy + sw * sw + sh * sh) + di * di;
        } else {
            acc += LAMBDA_NO_OBJ * c2f * c2f;
        }
    }

    // ===== block reduction =====
    __shared__ float warp_sums[NTHREADS >> 5];
    float wsum = warp_reduce(acc);
    int lane = tx & 31;
    int wid  = tx >> 5;
    if (lane == 0) warp_sums[wid] = wsum;
    __syncthreads();

    if (wid == 0) {
        float v = (lane < (NTHREADS >> 5)) ? warp_sums[lane] : 0.0f;
        v = warp_reduce(v);
        if (lane == 0) {
            // PDL: wait for the concurrently-running zero kernel to finish
            // before the first write that depends on it.
            cudaGridDependencySynchronize();
            atomicAdd(out, v);
        }
    }
}

extern "C" void kernel_launch(void* const* d_in, const int* in_sizes, int n_in,
                              void* d_out, int out_size) {
    const float*  main_boxes   = (const float*) d_in[0];
    const float4* pred_boxes   = (const float4*)d_in[1];
    const float*  conf         = (const float*) d_in[2];
    const float4* gmp          = (const float4*)d_in[3];
    const float4* gpp          = (const float4*)d_in[4];
    const int*    matched_main = (const int*)   d_in[5];
    const float*  matched_iou  = (const float*) d_in[6];
    float* out = (float*)d_out;

    int P   = in_sizes[2];      // 32768
    int NP4 = in_sizes[3] / 4;  // 327680

    int chunk  = (NP4 + NBLOCKS - 1) / NBLOCKS;  // 2215
    int bchunk = (P   + NBLOCKS - 1) / NBLOCKS;  // 222

    zero_out_kernel<<<1, 1>>>(out);

    // Launch the main kernel with programmatic dependent launch so it
    // overlaps the zero kernel; the in-kernel cudaGridDependencySynchronize
    // enforces ordering only where needed (before the atomic tail).
    cudaLaunchConfig_t cfg = {};
    cfg.gridDim  = dim3(NBLOCKS, 1, 1);
    cfg.blockDim = dim3(NTHREADS, 1, 1);
    cfg.dynamicSmemBytes = 0;
    cfg.stream = 0;
    cudaLaunchAttribute attrs[1];
    attrs[0].id = cudaLaunchAttributeProgrammaticStreamSerialization;
    attrs[0].val.programmaticStreamSerializationAllowed = 1;
    cfg.attrs = attrs;
    cfg.numAttrs = 1;

    cudaLaunchKernelEx(&cfg, yolo_loss_kernel,
                       main_boxes, pred_boxes, conf, gmp, gpp,
                       matched_main, matched_iou, out, P, NP4, chunk, bchunk);
}